// round 7
// baseline (speedup 1.0000x reference)
#include <cuda_runtime.h>

// ---- problem constants ----
#define LFULL (1 << 20)
#define L1SZ  (1 << 19)
#define L2SZ  (1 << 18)
#define L3SZ  (1 << 17)

// ---- flattened output offsets (tuple order: lo3, yh0, yh1, yh2) ----
#define OFF_YH0 8388608L
#define OFF_YH1 41943040L
#define OFF_YH2 75497472L

// XOR swizzle on float4 index: permutes within 8-float4 (128B) groups so that
// dense writes AND stride-2/stride-4 float4 window reads are bank-conflict-free.
#define SW(f) ((f) ^ (((f) >> 3) & 7))

// Tiling: block = 512 level-3 outputs of one batch row; 256 threads.
// level-1 chunks: t in [0,264), p0 = P0-32+8t  (core t in [4,260))
// level-2 chunks: c in [0,130), n0 = N0-8+8c   (core c in [1,129))
// level-3 chunks: d in [0,128), m0 = M0+4d     (all core)
#define NXF4 1058   // float4's of x tile: sx[r] = x[8M0-68+r], r in [0,4232)

__global__ __launch_bounds__(256) void dtcwt1d_fused(
    const float* __restrict__ x,
    const float* __restrict__ h0o, const float* __restrict__ h1o,
    const float* __restrict__ h0a,
    float* __restrict__ out)
{
    __shared__ __align__(16) float4 SX[1064];  // 4232 floats (padded to 128B grp)
    __shared__ __align__(16) float4 S1[528];   // lo1: s1[u] = lo1[P0-32+u], u<2112
    __shared__ __align__(16) float4 S2[264];   // lo2: s2[v] = lo2[N0-8+v],  v<1040

    const int tid = threadIdx.x;
    const int b   = blockIdx.y;
    const int M0  = blockIdx.x * 512;
    const int N0  = 2 * M0;
    const int P0  = 4 * M0;
    const bool edge = (blockIdx.x == 0) || (blockIdx.x == gridDim.x - 1);

    const float* xb = x + (long)b * LFULL;
    const long gbase = 8L * M0 - 68;

    // ---- stage x tile into smem (dense LDG.128 -> swizzled STS.128) ----
    for (int j = tid; j < NXF4; j += 256) {
        const long g0 = gbase + 4L * j;
        float4 v;
        if (!edge) {
            v = *(const float4*)(xb + g0);
        } else {
            v.x = (g0     >= 0 && g0     < LFULL) ? xb[g0]     : 0.f;
            v.y = (g0 + 1 >= 0 && g0 + 1 < LFULL) ? xb[g0 + 1] : 0.f;
            v.z = (g0 + 2 >= 0 && g0 + 2 < LFULL) ? xb[g0 + 2] : 0.f;
            v.w = (g0 + 3 >= 0 && g0 + 3 < LFULL) ? xb[g0 + 3] : 0.f;
        }
        SX[SW(j)] = v;
    }
    __syncthreads();

    // ---- level 1: 8 outputs/chunk. w[k] = sx[16t+k], k in [0,24) ----
    // lo[j] = sum_s h0o[s] w[2j+2+s]   (x[2p-2+s])
    // hi[j] = sum_s h1o[s] w[2j+1+s]   (x[2p-3+s])
    {
        const float c0=h0o[0],c1=h0o[1],c2=h0o[2],c3=h0o[3],c4=h0o[4];
        const float d0=h1o[0],d1=h1o[1],d2=h1o[2],d3=h1o[3],
                    d4=h1o[4],d5=h1o[5],d6=h1o[6];
        float* yh0 = out + OFF_YH0 + (long)b * L1SZ;
        for (int t = tid; t < 264; t += 256) {
            float w[24];
            #pragma unroll
            for (int q = 0; q < 6; ++q) {
                const float4 v = SX[SW(4*t + q)];
                w[4*q] = v.x; w[4*q+1] = v.y; w[4*q+2] = v.z; w[4*q+3] = v.w;
            }
            float lo[8], hi[8];
            #pragma unroll
            for (int j = 0; j < 8; ++j) {
                lo[j] = c0*w[2*j+2] + c1*w[2*j+3] + c2*w[2*j+4]
                      + c3*w[2*j+5] + c4*w[2*j+6];
                hi[j] = d0*w[2*j+1] + d1*w[2*j+2] + d2*w[2*j+3] + d3*w[2*j+4]
                      + d4*w[2*j+5] + d5*w[2*j+6] + d6*w[2*j+7];
            }
            if (edge) {
                const int p0 = P0 - 32 + 8*t;
                #pragma unroll
                for (int j = 0; j < 8; ++j)
                    if (p0 + j < 0 || p0 + j >= L1SZ) lo[j] = 0.f;
            }
            S1[SW(2*t)]     = make_float4(lo[0], lo[1], lo[2], lo[3]);
            S1[SW(2*t + 1)] = make_float4(lo[4], lo[5], lo[6], lo[7]);
            if (t >= 4 && t < 260) {
                float* p = yh0 + P0 + 8*(t - 4);
                *(float4*)(p)     = make_float4(hi[0], hi[1], hi[2], hi[3]);
                *(float4*)(p + 4) = make_float4(hi[4], hi[5], hi[6], hi[7]);
            }
        }
    }
    __syncthreads();

    // ---- level 2: 8 outputs/chunk. a[k] = s1[16c+8+k], k in [0,32) ----
    // window for output j: a[2j+2 .. 2j+15]
    // Es = sum ae[s] a[2j+2+2s], Os = sum ao[s] a[2j+3+2s]
    // lo = Es+Os; hb = Os-Es; ha = sum ao[6-s] a[2j+2+2s] - sum ae[6-s] a[2j+3+2s]
    {
        float ae[7], ao[7];
        #pragma unroll
        for (int s = 0; s < 7; ++s) { ae[s] = h0a[2*s]; ao[s] = h0a[2*s+1]; }
        float* yh1 = out + OFF_YH1 + (long)b * (2L * L2SZ);
        if (tid < 130) {
            const int c = tid;
            float a[32];
            #pragma unroll
            for (int q = 0; q < 8; ++q) {
                const float4 v = S1[SW(4*c + 2 + q)];
                a[4*q] = v.x; a[4*q+1] = v.y; a[4*q+2] = v.z; a[4*q+3] = v.w;
            }
            float lo[8], ha[8], hb[8];
            #pragma unroll
            for (int j = 0; j < 8; ++j) {
                float Es = 0.f, Os = 0.f, Pu = 0.f, Qu = 0.f;
                #pragma unroll
                for (int s = 0; s < 7; ++s) {
                    const float ve = a[2*j + 2 + 2*s], vo = a[2*j + 3 + 2*s];
                    Es += ae[s]   * ve;  Os += ao[s]   * vo;
                    Pu += ao[6-s] * ve;  Qu += ae[6-s] * vo;
                }
                lo[j] = Es + Os;  hb[j] = Os - Es;  ha[j] = Pu - Qu;
            }
            if (edge) {
                const int n0 = N0 - 8 + 8*c;
                #pragma unroll
                for (int j = 0; j < 8; ++j)
                    if (n0 + j < 0 || n0 + j >= L2SZ) lo[j] = 0.f;
            }
            S2[SW(2*c)]     = make_float4(lo[0], lo[1], lo[2], lo[3]);
            S2[SW(2*c + 1)] = make_float4(lo[4], lo[5], lo[6], lo[7]);
            if (c >= 1 && c < 129) {
                const int n0 = N0 + 8*(c - 1);
                *(float4*)(yh1 + n0)            = make_float4(ha[0],ha[1],ha[2],ha[3]);
                *(float4*)(yh1 + n0 + 4)        = make_float4(ha[4],ha[5],ha[6],ha[7]);
                *(float4*)(yh1 + L2SZ + n0)     = make_float4(hb[0],hb[1],hb[2],hb[3]);
                *(float4*)(yh1 + L2SZ + n0 + 4) = make_float4(hb[4],hb[5],hb[6],hb[7]);
            }
        }
    }
    __syncthreads();

    // ---- level 3: 4 outputs/chunk. bw[k] = s2[8d+k], k in [0,24) ----
    // window for output j: bw[2j+2 .. 2j+15]
    if (tid < 128) {
        float ae[7], ao[7];
        #pragma unroll
        for (int s = 0; s < 7; ++s) { ae[s] = h0a[2*s]; ao[s] = h0a[2*s+1]; }
        const int d = tid;
        float bw[24];
        #pragma unroll
        for (int q = 0; q < 6; ++q) {
            const float4 v = S2[SW(2*d + q)];
            bw[4*q] = v.x; bw[4*q+1] = v.y; bw[4*q+2] = v.z; bw[4*q+3] = v.w;
        }
        float lo[4], ha[4], hb[4];
        #pragma unroll
        for (int j = 0; j < 4; ++j) {
            float Es = 0.f, Os = 0.f, Pu = 0.f, Qu = 0.f;
            #pragma unroll
            for (int s = 0; s < 7; ++s) {
                const float ve = bw[2*j + 2 + 2*s], vo = bw[2*j + 3 + 2*s];
                Es += ae[s]   * ve;  Os += ao[s]   * vo;
                Pu += ao[6-s] * ve;  Qu += ae[6-s] * vo;
            }
            lo[j] = Es + Os;  hb[j] = Os - Es;  ha[j] = Pu - Qu;
        }
        float* olo = out + (long)b * L3SZ;
        float* yh2 = out + OFF_YH2 + (long)b * (2L * L3SZ);
        const int m = M0 + 4*d;
        *(float4*)(olo + m)        = make_float4(lo[0], lo[1], lo[2], lo[3]);
        *(float4*)(yh2 + m)        = make_float4(ha[0], ha[1], ha[2], ha[3]);
        *(float4*)(yh2 + L3SZ + m) = make_float4(hb[0], hb[1], hb[2], hb[3]);
    }
}

extern "C" void kernel_launch(void* const* d_in, const int* in_sizes, int n_in,
                              void* d_out, int out_size) {
    (void)in_sizes; (void)n_in; (void)out_size;
    // metadata order: x, h0o, h1o, h0a, h1a, h0b, h1b (qshift filters derived)
    dim3 grid(L3SZ / 512, 64);
    dtcwt1d_fused<<<grid, 256>>>(
        (const float*)d_in[0],
        (const float*)d_in[1], (const float*)d_in[2],
        (const float*)d_in[3],
        (float*)d_out);
}

// round 8
// speedup vs baseline: 1.1406x; 1.1406x over previous
#include <cuda_runtime.h>

// ---- problem constants ----
#define LFULL (1 << 20)
#define L1SZ  (1 << 19)
#define L2SZ  (1 << 18)
#define L3SZ  (1 << 17)

// ---- flattened output offsets (tuple order: lo3, yh0, yh1, yh2) ----
#define OFF_YH0 8388608L
#define OFF_YH1 41943040L
#define OFF_YH2 75497472L

// Per-warp tile: 64 level-3 outputs. 8 warps/block, grid.x = 256.
// Per-warp smem slice (floats):
//   xe[312], xo[312] : x planes, xe[k] = x[8M0-52+2k]
//   s1e[152], s1o[152]: lo1 planes, s1e[k] = lo1[P0-24+2k]
//   s2e[72],  s2o[72] : lo2 planes, s2e[k] = lo2[N0-8+2k]
#define WSLICE 1072
#define OXE 0
#define OXO 312
#define OS1E 624
#define OS1O 776
#define OS2E 928
#define OS2O 1000

__global__ __launch_bounds__(256) void dtcwt1d_warp(
    const float* __restrict__ x,
    const float* __restrict__ h0o, const float* __restrict__ h1o,
    const float* __restrict__ h0a,
    float* __restrict__ out)
{
    __shared__ __align__(16) float SM[8 * WSLICE];

    const int lane = threadIdx.x & 31;
    const int wid  = threadIdx.x >> 5;
    const int b    = blockIdx.y;
    const int wx   = blockIdx.x * 8 + wid;      // global warp tile index
    const int M0   = wx * 64;
    const int N0   = 2 * M0;
    const int P0   = 4 * M0;
    const bool edge = (wx == 0) || (wx == 2047);

    float* const W   = SM + wid * WSLICE;
    float* const xe  = W + OXE;
    float* const xo  = W + OXO;
    float* const s1e = W + OS1E;
    float* const s1o = W + OS1O;
    float* const s2e = W + OS2E;
    float* const s2o = W + OS2O;

    const float* xb = x + (long)b * LFULL;

    // ---- stage x window [8M0-52, 8M0+564) -> even/odd planes ----
    for (int j = lane; j < 154; j += 32) {
        const long g0 = 8L * M0 - 52 + 4L * j;
        float4 v;
        if (!edge) {
            v = *(const float4*)(xb + g0);
        } else {
            v.x = (g0     >= 0 && g0     < LFULL) ? xb[g0]     : 0.f;
            v.y = (g0 + 1 >= 0 && g0 + 1 < LFULL) ? xb[g0 + 1] : 0.f;
            v.z = (g0 + 2 >= 0 && g0 + 2 < LFULL) ? xb[g0 + 2] : 0.f;
            v.w = (g0 + 3 >= 0 && g0 + 3 < LFULL) ? xb[g0 + 3] : 0.f;
        }
        *(float2*)(xe + 2 * j) = make_float2(v.x, v.z);
        *(float2*)(xo + 2 * j) = make_float2(v.y, v.w);
    }
    __syncwarp();

    // ---- level 1: 76 groups of 4 (lo1 p in [P0-24, P0+280)); hi1 core g in [6,70)
    {
        const float c0=h0o[0],c1=h0o[1],c2=h0o[2],c3=h0o[3],c4=h0o[4];
        const float d0=h1o[0],d1=h1o[1],d2=h1o[2],d3=h1o[3],
                    d4=h1o[4],d5=h1o[5],d6=h1o[6];
        float* yh0 = out + OFF_YH0 + (long)b * L1SZ;
        for (int g = lane; g < 76; g += 32) {
            const int lp0 = 4 * g;
            const float4 A0 = *(const float4*)(xe + lp0);
            const float4 A1 = *(const float4*)(xe + lp0 + 4);
            const float4 B0 = *(const float4*)(xo + lp0);
            const float4 B1 = *(const float4*)(xo + lp0 + 4);
            const float E[8] = {A0.x, A0.y, A0.z, A0.w, A1.x, A1.y, A1.z, A1.w};
            const float O[8] = {B0.x, B0.y, B0.z, B0.w, B1.x, B1.y, B1.z, B1.w};
            float lo[4], hi[4];
            #pragma unroll
            for (int j = 0; j < 4; ++j) {
                lo[j] = c0 * E[j + 1] + c2 * E[j + 2] + c4 * E[j + 3]
                      + c1 * O[j + 1] + c3 * O[j + 2];
                hi[j] = d0 * O[j] + d2 * O[j + 1] + d4 * O[j + 2] + d6 * O[j + 3]
                      + d1 * E[j + 1] + d3 * E[j + 2] + d5 * E[j + 3];
            }
            if (edge) {
                const int pb = P0 - 24 + lp0;
                #pragma unroll
                for (int j = 0; j < 4; ++j)
                    if (pb + j < 0 || pb + j >= L1SZ) lo[j] = 0.f;
            }
            *(float2*)(s1e + 2 * g) = make_float2(lo[0], lo[2]);
            *(float2*)(s1o + 2 * g) = make_float2(lo[1], lo[3]);
            if (g >= 6 && g < 70)
                *(float4*)(yh0 + P0 + 4 * (g - 6)) =
                    make_float4(hi[0], hi[1], hi[2], hi[3]);
        }
    }
    __syncwarp();

    // ---- level 2: 36 groups of 4 (lo2 n in [N0-8, N0+136)); core g in [2,34)
    {
        float ae[7], ao[7];
        #pragma unroll
        for (int s = 0; s < 7; ++s) { ae[s] = h0a[2 * s]; ao[s] = h0a[2 * s + 1]; }
        float* yh1 = out + OFF_YH1 + (long)b * (2L * L2SZ);
        for (int g = lane; g < 36; g += 32) {
            const int ln0 = 4 * g;
            const float4 A0 = *(const float4*)(s1e + ln0);
            const float4 A1 = *(const float4*)(s1e + ln0 + 4);
            const float4 A2 = *(const float4*)(s1e + ln0 + 8);
            const float4 B0 = *(const float4*)(s1o + ln0);
            const float4 B1 = *(const float4*)(s1o + ln0 + 4);
            const float4 B2 = *(const float4*)(s1o + ln0 + 8);
            const float we[12] = {A0.x, A0.y, A0.z, A0.w, A1.x, A1.y,
                                  A1.z, A1.w, A2.x, A2.y, A2.z, A2.w};
            const float wo[12] = {B0.x, B0.y, B0.z, B0.w, B1.x, B1.y,
                                  B1.z, B1.w, B2.x, B2.y, B2.z, B2.w};
            float lo[4], ha[4], hb[4];
            #pragma unroll
            for (int j = 0; j < 4; ++j) {
                float Es = 0.f, Os = 0.f, Pu = 0.f, Qu = 0.f;
                #pragma unroll
                for (int s = 0; s < 7; ++s) {
                    const float ve = we[j + 1 + s], vo = wo[j + 1 + s];
                    Es += ae[s]   * ve;  Os += ao[s]   * vo;
                    Pu += ao[6-s] * ve;  Qu += ae[6-s] * vo;
                }
                lo[j] = Es + Os;  hb[j] = Os - Es;  ha[j] = Pu - Qu;
            }
            if (edge) {
                const int nb = N0 - 8 + ln0;
                #pragma unroll
                for (int j = 0; j < 4; ++j)
                    if (nb + j < 0 || nb + j >= L2SZ) lo[j] = 0.f;
            }
            *(float2*)(s2e + 2 * g) = make_float2(lo[0], lo[2]);
            *(float2*)(s2o + 2 * g) = make_float2(lo[1], lo[3]);
            if (g >= 2 && g < 34) {
                const int n_out = N0 + 4 * (g - 2);
                *(float4*)(yh1 + n_out)        = make_float4(ha[0],ha[1],ha[2],ha[3]);
                *(float4*)(yh1 + L2SZ + n_out) = make_float4(hb[0],hb[1],hb[2],hb[3]);
            }
        }
    }
    __syncwarp();

    // ---- level 3: 16 groups of 4 (m in [M0, M0+64)) ----
    if (lane < 16) {
        float ae[7], ao[7];
        #pragma unroll
        for (int s = 0; s < 7; ++s) { ae[s] = h0a[2 * s]; ao[s] = h0a[2 * s + 1]; }
        const int lm0 = 4 * lane;
        const float4 A0 = *(const float4*)(s2e + lm0);
        const float4 A1 = *(const float4*)(s2e + lm0 + 4);
        const float4 A2 = *(const float4*)(s2e + lm0 + 8);
        const float4 B0 = *(const float4*)(s2o + lm0);
        const float4 B1 = *(const float4*)(s2o + lm0 + 4);
        const float4 B2 = *(const float4*)(s2o + lm0 + 8);
        const float we[12] = {A0.x, A0.y, A0.z, A0.w, A1.x, A1.y,
                              A1.z, A1.w, A2.x, A2.y, A2.z, A2.w};
        const float wo[12] = {B0.x, B0.y, B0.z, B0.w, B1.x, B1.y,
                              B1.z, B1.w, B2.x, B2.y, B2.z, B2.w};
        float lo[4], ha[4], hb[4];
        #pragma unroll
        for (int j = 0; j < 4; ++j) {
            float Es = 0.f, Os = 0.f, Pu = 0.f, Qu = 0.f;
            #pragma unroll
            for (int s = 0; s < 7; ++s) {
                const float ve = we[j + 1 + s], vo = wo[j + 1 + s];
                Es += ae[s]   * ve;  Os += ao[s]   * vo;
                Pu += ao[6-s] * ve;  Qu += ae[6-s] * vo;
            }
            lo[j] = Es + Os;  hb[j] = Os - Es;  ha[j] = Pu - Qu;
        }
        float* olo = out + (long)b * L3SZ;
        float* yh2 = out + OFF_YH2 + (long)b * (2L * L3SZ);
        const int m = M0 + lm0;
        *(float4*)(olo + m)        = make_float4(lo[0], lo[1], lo[2], lo[3]);
        *(float4*)(yh2 + m)        = make_float4(ha[0], ha[1], ha[2], ha[3]);
        *(float4*)(yh2 + L3SZ + m) = make_float4(hb[0], hb[1], hb[2], hb[3]);
    }
}

extern "C" void kernel_launch(void* const* d_in, const int* in_sizes, int n_in,
                              void* d_out, int out_size) {
    (void)in_sizes; (void)n_in; (void)out_size;
    // metadata order: x, h0o, h1o, h0a, h1a, h0b, h1b (qshift filters derived)
    dim3 grid(256, 64);
    dtcwt1d_warp<<<grid, 256>>>(
        (const float*)d_in[0],
        (const float*)d_in[1], (const float*)d_in[2],
        (const float*)d_in[3],
        (float*)d_out);
}